// round 1
// baseline (speedup 1.0000x reference)
#include <cuda_runtime.h>
#include <math.h>

#define NPTS   2048
#define NT     256
#define EPT    8          // elements per thread
#define NW     (NT/32)    // warps per block
#define MAXPTS 100
#define F_INF  (__int_as_float(0x7f800000))

__global__ __launch_bounds__(NT, 1)
void ph_kernel(const float* __restrict__ x,
               const float* __restrict__ filt,
               float* __restrict__ out,
               int B, int F)
{
    __shared__ float sx[NPTS], sy[NPTS], sz[NPTS], ssq[NPTS];
    __shared__ __align__(16) float sdeath[NPTS];
    __shared__ float wrv[2][NW];
    __shared__ int   wri[2][NW];

    const int b    = blockIdx.x;
    const int tid  = threadIdx.x;
    const int lane = tid & 31;
    const int wid  = tid >> 5;

    const float* xb = x + (long)b * NPTS * 3;

    // ---- load points: registers (working copy) + smem SoA (pristine, for broadcast) ----
    float rx[EPT], ry[EPT], rz[EPT], rsq[EPT], mk[EPT];
    #pragma unroll
    for (int e = 0; e < EPT; e++) {
        int i = (tid << 3) + e;
        float a = xb[3*i + 0];
        float c = xb[3*i + 1];
        float d = xb[3*i + 2];
        rx[e] = a; ry[e] = c; rz[e] = d;
        float s = fmaf(a, a, fmaf(c, c, d * d));
        rsq[e] = s; mk[e] = F_INF;
        sx[i] = a; sy[i] = c; sz[i] = d; ssq[i] = s;
    }
    __syncthreads();

    // ---- Prim's MST: 2047 steps, one barrier per step ----
    int j = 0;      // frontier vertex just added (all threads agree)
    int p = 0;      // double-buffer parity for warp-leader slots
    const float inf = F_INF;

    for (int step = 0; step < NPTS - 1; step++) {
        // broadcast frontier coords (same-address LDS -> conflict-free broadcast)
        float m2x  = -2.0f * sx[j];
        float m2y  = -2.0f * sy[j];
        float m2z  = -2.0f * sz[j];
        float base = ssq[j];

        float bv = inf; int bi = 0;
        #pragma unroll
        for (int e = 0; e < EPT; e++) {
            int gi = (tid << 3) + e;
            bool rem = (gi == j);
            rsq[e] = rem ? inf : rsq[e];          // permanent poison of removed vertex
            float acc = fmaf(m2x, rx[e], rsq[e] + base);
            acc = fmaf(m2y, ry[e], acc);
            acc = fmaf(m2z, rz[e], acc);          // d^2(j, gi)  (INF once removed)
            float m = fminf(mk[e], acc);
            m = rem ? inf : m;
            mk[e] = m;
            if (m < bv) { bv = m; bi = gi; }
        }

        // warp argmin reduce (exact float compare)
        #pragma unroll
        for (int off = 16; off; off >>= 1) {
            float ov = __shfl_down_sync(0xffffffffu, bv, off);
            int   oi = __shfl_down_sync(0xffffffffu, bi, off);
            if (ov < bv) { bv = ov; bi = oi; }
        }
        if (lane == 0) { wrv[p][wid] = bv; wri[p][wid] = bi; }
        __syncthreads();

        // redundant cross-warp final reduce in every thread (avoids 2nd barrier)
        float fv = wrv[p][0]; int fj = wri[p][0];
        #pragma unroll
        for (int k = 1; k < NW; k++) {
            float v = wrv[p][k];
            if (v < fv) { fv = v; fj = wri[p][k]; }
        }
        if (tid == 0) sdeath[step] = fv;   // record d^2 death (exact)
        j = fj;
        p ^= 1;
    }
    __syncthreads();

    // ---- convert d^2 -> death = sqrt(max(d2,0)); pad slot 2047 with +INF ----
    #pragma unroll
    for (int e = 0; e < EPT; e++) {
        int i = (tid << 3) + e;
        float d2 = sdeath[i];
        sdeath[i] = (i < NPTS - 1) ? sqrtf(fmaxf(d2, 0.0f)) : inf;
    }
    __syncthreads();

    const long dgm_base = (long)b * 3 * MAXPTS * 2;                     // diagrams [B,3,100,2]
    const long bet_base = (long)B * 3 * MAXPTS * 2 + (long)b * 3 * F;   // betti    [B,3,F]

    // ---- zero-fill H1/H2 diagram slices and betti curves ----
    for (int i = tid; i < 2 * MAXPTS * 2; i += NT)
        out[dgm_base + MAXPTS * 2 + i] = 0.0f;
    for (int i = tid; i < 2 * F; i += NT)
        out[bet_base + F + i] = 0.0f;

    // ---- Betti-0 curve: one threshold per thread; same-address float4 LDS scan ----
    if (tid < F) {
        float ff = filt[tid];
        int cnt = 0;
        for (int i = 0; i < NPTS; i += 4) {
            float4 v = *reinterpret_cast<const float4*>(&sdeath[i]);
            cnt += (v.x <= ff) + (v.y <= ff) + (v.z <= ff) + (v.w <= ff);
        }
        out[bet_base + tid] = (float)(NPTS - cnt);   // pad=INF never counts
    }
    __syncthreads();

    // ---- top-100 deaths, descending: iterative max extraction ----
    int jp = -1;   // removed last iteration (not yet persisted when scanned)
    p = 0;
    for (int k = 0; k < MAXPTS; k++) {
        float bv = -1.0f; int bi = 0;
        #pragma unroll
        for (int e = 0; e < EPT; e++) {
            int gi = (tid << 3) + e;
            float v = sdeath[gi];
            v = (gi == jp || gi == NPTS - 1) ? -1.0f : v;  // mask pending removal + INF pad
            if (v > bv) { bv = v; bi = gi; }
        }
        #pragma unroll
        for (int off = 16; off; off >>= 1) {
            float ov = __shfl_down_sync(0xffffffffu, bv, off);
            int   oi = __shfl_down_sync(0xffffffffu, bi, off);
            if (ov > bv) { bv = ov; bi = oi; }
        }
        if (lane == 0) { wrv[p][wid] = bv; wri[p][wid] = bi; }
        if (tid == 0 && jp >= 0) sdeath[jp] = -1.0f;  // persist removal (benign race: masked)
        __syncthreads();

        float fv = wrv[p][0]; int fj = wri[p][0];
        #pragma unroll
        for (int kk = 1; kk < NW; kk++) {
            float v = wrv[p][kk];
            if (v > fv) { fv = v; fj = wri[p][kk]; }
        }
        if (tid == 0) {
            out[dgm_base + 2 * k + 0] = 0.0f;   // birth
            out[dgm_base + 2 * k + 1] = fv;     // death
        }
        jp = fj;
        p ^= 1;
    }
}

extern "C" void kernel_launch(void* const* d_in, const int* in_sizes, int n_in,
                              void* d_out, int out_size)
{
    const float* x    = (const float*)d_in[0];
    const float* filt = (const float*)d_in[1];
    float* out        = (float*)d_out;

    int B = in_sizes[0] / (NPTS * 3);
    int F = in_sizes[1];

    ph_kernel<<<B, NT>>>(x, filt, out, B, F);
}

// round 2
// speedup vs baseline: 1.2114x; 1.2114x over previous
#include <cuda_runtime.h>
#include <math.h>

#define NPTS   2048
#define NT     256
#define EPT    8
#define NW     (NT/32)
#define MAXPTS 100
#define F_INF  (__int_as_float(0x7f800000))

typedef unsigned long long u64;
typedef unsigned int       u32;

static __device__ __forceinline__ u64 umin64(u64 a, u64 b) { return a < b ? a : b; }
static __device__ __forceinline__ u64 umax64(u64 a, u64 b) { return a > b ? a : b; }

__global__ __launch_bounds__(NT, 1)
void ph_kernel(const float* __restrict__ x,
               const float* __restrict__ filt,
               float* __restrict__ out,
               int B, int F)
{
    __shared__ float4 spt[NPTS];                 // (-2x, -2y, -2z, |x|^2)
    __shared__ __align__(16) float sdeath[NPTS];
    __shared__ u64 wred[2][NW];

    const int b    = blockIdx.x;
    const int tid  = threadIdx.x;
    const int lane = tid & 31;
    const int wid  = tid >> 5;
    const int gbase = tid << 3;

    const float* xb = x + (long)b * NPTS * 3;

    // ---- load: raw coords in registers, premultiplied SoA->float4 in smem ----
    float rx[EPT], ry[EPT], rz[EPT], rsq[EPT], mk[EPT];
    #pragma unroll
    for (int e = 0; e < EPT; e++) {
        int i = gbase + e;
        float a = xb[3*i + 0];
        float c = xb[3*i + 1];
        float d = xb[3*i + 2];
        rx[e] = a; ry[e] = c; rz[e] = d;
        float s = fmaf(a, a, fmaf(c, c, d * d));
        rsq[e] = s; mk[e] = F_INF;
        spt[i] = make_float4(-2.0f * a, -2.0f * c, -2.0f * d, s);
    }
    __syncthreads();

    // ---- Prim's MST: 2047 steps, one barrier/step, redux-based argmin ----
    int j = 0;
    int p = 0;
    const float inf = F_INF;

    for (int step = 0; step < NPTS - 1; step++) {
        float4 pj = spt[j];                      // single LDS.128 broadcast

        float tm = inf; u32 ti = 0;
        #pragma unroll
        for (int e = 0; e < EPT; e++) {
            int gi = gbase + e;
            bool rem = (gi == j);
            rsq[e] = rem ? inf : rsq[e];         // permanent poison of removed vertex
            float acc = fmaf(pj.x, rx[e], rsq[e] + pj.w);
            acc = fmaf(pj.y, ry[e], acc);
            acc = fmaf(pj.z, rz[e], acc);
            acc = fmaxf(acc, 0.0f);              // >=0 -> u32-bit ordering exact
            float m = fminf(mk[e], acc);
            m = rem ? inf : m;
            mk[e] = m;
            if (m < tm) { tm = m; ti = (u32)gi; }
        }

        // warp argmin via two hardware reductions (exact: tm >= 0)
        u32 vb = __float_as_uint(tm);
        u32 r1 = __reduce_min_sync(0xffffffffu, vb);
        u32 ik = (vb == r1) ? ti : 0xffffffffu;
        u32 r2 = __reduce_min_sync(0xffffffffu, ik);

        if (lane == 0) wred[p][wid] = ((u64)r1 << 32) | (u64)r2;
        __syncthreads();

        // cross-warp final reduce: 3-deep u64 min tree, redundant in all threads
        u64 m0 = umin64(wred[p][0], wred[p][1]);
        u64 m1 = umin64(wred[p][2], wred[p][3]);
        u64 m2 = umin64(wred[p][4], wred[p][5]);
        u64 m3 = umin64(wred[p][6], wred[p][7]);
        m0 = umin64(m0, m1); m2 = umin64(m2, m3); m0 = umin64(m0, m2);

        if (tid == 0) sdeath[step] = __uint_as_float((u32)(m0 >> 32));  // d^2 death
        j = (int)(u32)m0;
        p ^= 1;
    }
    __syncthreads();

    // ---- d^2 -> death = sqrt(d2); pad slot 2047 with +INF ----
    #pragma unroll
    for (int e = 0; e < EPT; e++) {
        int i = gbase + e;
        float d2 = sdeath[i];
        sdeath[i] = (i < NPTS - 1) ? sqrtf(d2) : inf;   // d2 already clamped >= 0
    }
    __syncthreads();

    const long dgm_base = (long)b * 3 * MAXPTS * 2;                     // diagrams [B,3,100,2]
    const long bet_base = (long)B * 3 * MAXPTS * 2 + (long)b * 3 * F;   // betti    [B,3,F]

    // ---- zero-fill H1/H2 diagram slices and betti curves ----
    for (int i = tid; i < 2 * MAXPTS * 2; i += NT)
        out[dgm_base + MAXPTS * 2 + i] = 0.0f;
    for (int i = tid; i < 2 * F; i += NT)
        out[bet_base + F + i] = 0.0f;

    // ---- Betti-0: one threshold/thread, float4 smem scan (pad=INF never counts) ----
    if (tid < F) {
        float ff = filt[tid];
        int cnt = 0;
        for (int i = 0; i < NPTS; i += 4) {
            float4 v = *reinterpret_cast<const float4*>(&sdeath[i]);
            cnt += (v.x <= ff) + (v.y <= ff) + (v.z <= ff) + (v.w <= ff);
        }
        out[bet_base + tid] = (float)(NPTS - cnt);
    }
    __syncthreads();

    // ---- top-100 deaths desc: iterative max extraction (redux-based) ----
    // Masked/removed entries become 0.0f; deaths >= 0 so u32-bit max ordering exact.
    // Emitting 0 for exhausted/tied-at-zero slots is value-correct.
    int jp = -1;
    p = 0;
    for (int k = 0; k < MAXPTS; k++) {
        float tv = 0.0f; u32 ti = 0;
        #pragma unroll
        for (int e = 0; e < EPT; e++) {
            int gi = gbase + e;
            float v = sdeath[gi];
            v = (gi == jp || gi == NPTS - 1) ? 0.0f : v;   // mask pending removal + INF pad
            if (v > tv) { tv = v; ti = (u32)gi; }
        }
        u32 vb = __float_as_uint(tv);
        u32 r1 = __reduce_max_sync(0xffffffffu, vb);
        u32 ik = (vb == r1) ? ti : 0u;
        u32 r2 = __reduce_max_sync(0xffffffffu, ik);

        if (lane == 0) wred[p][wid] = ((u64)r1 << 32) | (u64)r2;
        if (tid == 0 && jp >= 0) sdeath[jp] = 0.0f;        // persist removal
        __syncthreads();

        u64 m0 = umax64(wred[p][0], wred[p][1]);
        u64 m1 = umax64(wred[p][2], wred[p][3]);
        u64 m2 = umax64(wred[p][4], wred[p][5]);
        u64 m3 = umax64(wred[p][6], wred[p][7]);
        m0 = umax64(m0, m1); m2 = umax64(m2, m3); m0 = umax64(m0, m2);

        if (tid == 0) {
            out[dgm_base + 2 * k + 0] = 0.0f;                         // birth
            out[dgm_base + 2 * k + 1] = __uint_as_float((u32)(m0 >> 32)); // death
        }
        jp = (int)(u32)m0;
        p ^= 1;
    }
}

extern "C" void kernel_launch(void* const* d_in, const int* in_sizes, int n_in,
                              void* d_out, int out_size)
{
    const float* x    = (const float*)d_in[0];
    const float* filt = (const float*)d_in[1];
    float* out        = (float*)d_out;

    int B = in_sizes[0] / (NPTS * 3);
    int F = in_sizes[1];

    ph_kernel<<<B, NT>>>(x, filt, out, B, F);
}